// round 1
// baseline (speedup 1.0000x reference)
#include <cuda_runtime.h>
#include <math.h>

#define DIM 768
#define NHEAD 12
#define HD 64
#define BATCH 8
#define SEQ 1024
#define TOKENS (BATCH*SEQ)   // 8192
#define QKV_N (3*DIM)        // 2304

// Scratch (no allocation allowed)
__device__ float g_qkv[TOKENS * QKV_N];   // [8192][2304]  q|k|v packed per token
__device__ float g_attn[TOKENS * DIM];    // [8192][768]   attention output (B,N,D)

// ---------------------------------------------------------------------------
// SGEMM: C[m][n] = sum_k A[m][k] * W[n][k] + bias[n]
// A: [M][K] row-major, W: [N][K] row-major. BM=BN=128, BK=16, 256 threads,
// 8x8 microtile. Tiles stored K-major (transposed) in smem for vectorized
// conflict-free fragment loads. Requires M%128==0, N%128==0, K%16==0.
// ---------------------------------------------------------------------------
__global__ __launch_bounds__(256) void sgemm_bias(
    const float* __restrict__ A, const float* __restrict__ Wt,
    const float* __restrict__ bias, float* __restrict__ C,
    int M, int N, int K)
{
    __shared__ float As[16][128];
    __shared__ float Bs[16][128];

    const int bm = blockIdx.y * 128;
    const int bn = blockIdx.x * 128;
    const int t  = threadIdx.x;
    const int ty = t >> 4;      // 0..15
    const int tx = t & 15;      // 0..15

    float acc[8][8];
#pragma unroll
    for (int i = 0; i < 8; i++)
#pragma unroll
        for (int j = 0; j < 8; j++) acc[i][j] = 0.f;

    for (int k0 = 0; k0 < K; k0 += 16) {
        // load A tile (128x16) transposed -> As[k][m]
#pragma unroll
        for (int l = 0; l < 2; l++) {
            int idx = t + l * 256;            // 0..511 float4 slots
            int r = idx >> 2, c4 = (idx & 3) * 4;
            float4 v = *(const float4*)(A + (size_t)(bm + r) * K + k0 + c4);
            As[c4 + 0][r] = v.x; As[c4 + 1][r] = v.y;
            As[c4 + 2][r] = v.z; As[c4 + 3][r] = v.w;
        }
        // load W tile (128x16) transposed -> Bs[k][n]
#pragma unroll
        for (int l = 0; l < 2; l++) {
            int idx = t + l * 256;
            int r = idx >> 2, c4 = (idx & 3) * 4;
            float4 v = *(const float4*)(Wt + (size_t)(bn + r) * K + k0 + c4);
            Bs[c4 + 0][r] = v.x; Bs[c4 + 1][r] = v.y;
            Bs[c4 + 2][r] = v.z; Bs[c4 + 3][r] = v.w;
        }
        __syncthreads();

#pragma unroll
        for (int kk = 0; kk < 16; kk++) {
            float a[8], b[8];
            *(float4*)(a)     = *(const float4*)&As[kk][ty * 8];
            *(float4*)(a + 4) = *(const float4*)&As[kk][ty * 8 + 4];
            *(float4*)(b)     = *(const float4*)&Bs[kk][tx * 8];
            *(float4*)(b + 4) = *(const float4*)&Bs[kk][tx * 8 + 4];
#pragma unroll
            for (int i = 0; i < 8; i++)
#pragma unroll
                for (int j = 0; j < 8; j++)
                    acc[i][j] = fmaf(a[i], b[j], acc[i][j]);
        }
        __syncthreads();
    }

#pragma unroll
    for (int i = 0; i < 8; i++) {
        int m = bm + ty * 8 + i;
#pragma unroll
        for (int j = 0; j < 8; j += 4) {
            int n = bn + tx * 8 + j;
            float4 v;
            v.x = acc[i][j + 0] + bias[n + 0];
            v.y = acc[i][j + 1] + bias[n + 1];
            v.z = acc[i][j + 2] + bias[n + 2];
            v.w = acc[i][j + 3] + bias[n + 3];
            *(float4*)(C + (size_t)m * N + n) = v;
        }
    }
}

// ---------------------------------------------------------------------------
// LayerNorm over each 64-wide head segment of q and k (in place in g_qkv).
// One warp per (token, part in {q,k}, head). gamma/beta length 64.
// ---------------------------------------------------------------------------
__global__ __launch_bounds__(256) void qk_layernorm(
    float* __restrict__ qkv, const float* __restrict__ gamma,
    const float* __restrict__ beta)
{
    int gwarp = (blockIdx.x * blockDim.x + threadIdx.x) >> 5;
    int lane  = threadIdx.x & 31;
    // gwarp -> (m, p, h)
    int h = gwarp % NHEAD;
    int tmp = gwarp / NHEAD;
    int p = tmp & 1;
    int m = tmp >> 1;
    if (m >= TOKENS) return;

    float* row = qkv + (size_t)m * QKV_N + p * DIM + h * HD;
    float2 v = *(float2*)(row + lane * 2);

    float s = v.x + v.y;
#pragma unroll
    for (int o = 16; o; o >>= 1) s += __shfl_xor_sync(0xffffffffu, s, o);
    float mu = s * (1.f / 64.f);
    float dx = v.x - mu, dy = v.y - mu;
    float vs = dx * dx + dy * dy;
#pragma unroll
    for (int o = 16; o; o >>= 1) vs += __shfl_xor_sync(0xffffffffu, vs, o);
    float rstd = rsqrtf(vs * (1.f / 64.f) + 1e-5f);

    float2 r;
    r.x = dx * rstd * gamma[lane * 2 + 0] + beta[lane * 2 + 0];
    r.y = dy * rstd * gamma[lane * 2 + 1] + beta[lane * 2 + 1];
    *(float2*)(row + lane * 2) = r;
}

// ---------------------------------------------------------------------------
// Flash-style attention, fp32. One block per (b*h, q-tile of 64).
// BM=BN=64, hd=64, 256 threads, 4x4 microtiles. Online softmax.
// smem: Qs[d][i] (64x64), Vs[j][d] (64x64), KPs (64x68) shared between
// K-transposed tile and the P tile (P written after GEMM1 completes).
// ---------------------------------------------------------------------------
#define PW 68
__global__ __launch_bounds__(256) void attn_kernel(
    const float* __restrict__ qkv, float* __restrict__ out)
{
    extern __shared__ float sm[];
    float* Qs  = sm;                 // Qs[d*64 + i]
    float* Vs  = sm + 64 * 64;       // Vs[j*64 + d]
    float* KPs = sm + 2 * 64 * 64;   // Ks[d*PW + j]  /  Ps[j*PW + i]

    const int bh = blockIdx.x;            // 0..95
    const int b = bh / NHEAD, h = bh % NHEAD;
    const int q0 = blockIdx.y * 64;
    const int t = threadIdx.x;
    const int ty = t >> 4, tx = t & 15;

    const size_t base = (size_t)b * SEQ * QKV_N + (size_t)h * HD;

    // Load Q tile transposed: Qs[d][i]
#pragma unroll
    for (int l = 0; l < 4; l++) {
        int idx = t + l * 256;             // 0..1023 float4 slots
        int r = idx >> 4, c4 = (idx & 15) * 4;
        float4 v = *(const float4*)(qkv + base + (size_t)(q0 + r) * QKV_N + c4);
        Qs[(c4 + 0) * 64 + r] = v.x; Qs[(c4 + 1) * 64 + r] = v.y;
        Qs[(c4 + 2) * 64 + r] = v.z; Qs[(c4 + 3) * 64 + r] = v.w;
    }

    float m_old[4], lsum[4], oacc[4][4];
#pragma unroll
    for (int i = 0; i < 4; i++) {
        m_old[i] = -1e30f; lsum[i] = 0.f;
#pragma unroll
        for (int d = 0; d < 4; d++) oacc[i][d] = 0.f;
    }

    const float scale = 0.125f;  // 64^-0.5

    for (int kv = 0; kv < SEQ; kv += 64) {
        // Load K tile transposed -> KPs[d][j]; V tile row-major -> Vs[j][d]
#pragma unroll
        for (int l = 0; l < 4; l++) {
            int idx = t + l * 256;
            int r = idx >> 4, c4 = (idx & 15) * 4;
            const float* krow = qkv + base + DIM + (size_t)(kv + r) * QKV_N;
            float4 kk4 = *(const float4*)(krow + c4);
            KPs[(c4 + 0) * PW + r] = kk4.x; KPs[(c4 + 1) * PW + r] = kk4.y;
            KPs[(c4 + 2) * PW + r] = kk4.z; KPs[(c4 + 3) * PW + r] = kk4.w;
            const float* vrow = qkv + base + 2 * DIM + (size_t)(kv + r) * QKV_N;
            *(float4*)(Vs + r * 64 + c4) = *(const float4*)(vrow + c4);
        }
        __syncthreads();

        // GEMM1: s[i][j] = sum_d Qs[d][ty*4+i] * Ks[d][tx*4+j]
        float s[4][4];
#pragma unroll
        for (int i = 0; i < 4; i++)
#pragma unroll
            for (int j = 0; j < 4; j++) s[i][j] = 0.f;
#pragma unroll 8
        for (int d = 0; d < 64; d++) {
            float a[4], bb[4];
            *(float4*)a  = *(const float4*)&Qs[d * 64 + ty * 4];
            *(float4*)bb = *(const float4*)&KPs[d * PW + tx * 4];
#pragma unroll
            for (int i = 0; i < 4; i++)
#pragma unroll
                for (int j = 0; j < 4; j++)
                    s[i][j] = fmaf(a[i], bb[j], s[i][j]);
        }

        // Online softmax (row groups of 16 lanes share ty)
        float p[4][4];
#pragma unroll
        for (int i = 0; i < 4; i++) {
            float mx = -1e30f;
#pragma unroll
            for (int j = 0; j < 4; j++) {
                s[i][j] *= scale;
                mx = fmaxf(mx, s[i][j]);
            }
#pragma unroll
            for (int o = 8; o; o >>= 1)
                mx = fmaxf(mx, __shfl_xor_sync(0xffffffffu, mx, o));
            float m_new = fmaxf(m_old[i], mx);
            float alpha = __expf(m_old[i] - m_new);
            float ls = 0.f;
#pragma unroll
            for (int j = 0; j < 4; j++) {
                p[i][j] = __expf(s[i][j] - m_new);
                ls += p[i][j];
            }
#pragma unroll
            for (int o = 8; o; o >>= 1)
                ls += __shfl_xor_sync(0xffffffffu, ls, o);
            lsum[i] = lsum[i] * alpha + ls;
#pragma unroll
            for (int d = 0; d < 4; d++) oacc[i][d] *= alpha;
            m_old[i] = m_new;
        }
        __syncthreads();   // all done reading Ks

        // Store P transposed: Ps[j][i]
#pragma unroll
        for (int j = 0; j < 4; j++) {
            float4 v = make_float4(p[0][j], p[1][j], p[2][j], p[3][j]);
            *(float4*)&KPs[(tx * 4 + j) * PW + ty * 4] = v;
        }
        __syncthreads();

        // GEMM2: oacc[i][d] += sum_j Ps[j][ty*4+i] * Vs[j][tx*4+d]
#pragma unroll 8
        for (int j = 0; j < 64; j++) {
            float pa[4], pv[4];
            *(float4*)pa = *(const float4*)&KPs[j * PW + ty * 4];
            *(float4*)pv = *(const float4*)&Vs[j * 64 + tx * 4];
#pragma unroll
            for (int i = 0; i < 4; i++)
#pragma unroll
                for (int d = 0; d < 4; d++)
                    oacc[i][d] = fmaf(pa[i], pv[d], oacc[i][d]);
        }
        __syncthreads();
    }

    // Write out[b][q0+i][h*64 + d]
#pragma unroll
    for (int i = 0; i < 4; i++) {
        int row = q0 + ty * 4 + i;
        float inv = 1.f / lsum[i];
        float4 v = make_float4(oacc[i][0] * inv, oacc[i][1] * inv,
                               oacc[i][2] * inv, oacc[i][3] * inv);
        *(float4*)(out + ((size_t)b * SEQ + row) * DIM + h * HD + tx * 4) = v;
    }
}

// ---------------------------------------------------------------------------
extern "C" void kernel_launch(void* const* d_in, const int* in_sizes, int n_in,
                              void* d_out, int out_size)
{
    const float* x      = (const float*)d_in[0];
    const float* qkv_w  = (const float*)d_in[1];
    const float* qkv_b  = (const float*)d_in[2];
    const float* proj_w = (const float*)d_in[3];
    const float* proj_b = (const float*)d_in[4];
    const float* qn_g   = (const float*)d_in[5];
    const float* qn_b   = (const float*)d_in[6];
    float* out = (float*)d_out;

    float* qkv;  cudaGetSymbolAddress((void**)&qkv, g_qkv);
    float* attn; cudaGetSymbolAddress((void**)&attn, g_attn);

    // 1) QKV projection: [8192,768] @ [2304,768]^T + b -> g_qkv
    sgemm_bias<<<dim3(QKV_N / 128, TOKENS / 128), 256>>>(
        x, qkv_w, qkv_b, qkv, TOKENS, QKV_N, DIM);

    // 2) LayerNorm q and k head segments in place
    {
        int warps = TOKENS * 2 * NHEAD;          // 196608
        int blocks = warps * 32 / 256;           // 24576
        qk_layernorm<<<blocks, 256>>>(qkv, qn_g, qn_b);
    }

    // 3) Attention
    {
        int smem = (2 * 64 * 64 + 64 * PW) * (int)sizeof(float);  // 50176
        static bool attr_set = false;
        if (!attr_set) {
            cudaFuncSetAttribute(attn_kernel,
                                 cudaFuncAttributeMaxDynamicSharedMemorySize, smem);
            attr_set = true;
        }
        attn_kernel<<<dim3(BATCH * NHEAD, SEQ / 64), 256, smem>>>(qkv, attn);
    }

    // 4) Output projection: [8192,768] @ [768,768]^T + b -> d_out
    sgemm_bias<<<dim3(DIM / 128, TOKENS / 128), 256>>>(
        attn, proj_w, proj_b, out, TOKENS, DIM, DIM);
}

// round 2
// speedup vs baseline: 4.6061x; 4.6061x over previous
#include <cuda_runtime.h>
#include <math.h>
#include <stdint.h>

#define DIM 768
#define NHEAD 12
#define HD 64
#define BATCH 8
#define SEQ 1024
#define TOKENS (BATCH*SEQ)   // 8192
#define QKV_N (3*DIM)        // 2304

// Scratch (no allocation allowed)
__device__ float g_qkv[TOKENS * QKV_N];   // [8192][2304]
__device__ float g_attn[TOKENS * DIM];    // [8192][768]

__device__ __forceinline__ float cvt_tf32(float x) {
    float r;
    asm("cvt.rna.tf32.f32 %0, %1;\n" : "=f"(r) : "f"(x));
    return r;
}

__device__ __forceinline__ float ex2f(float x) {
    float r;
    asm("ex2.approx.f32 %0, %1;\n" : "=f"(r) : "f"(x));
    return r;
}

__device__ __forceinline__ void mma_tf32(float c[4],
    uint32_t a0, uint32_t a1, uint32_t a2, uint32_t a3,
    uint32_t b0, uint32_t b1)
{
    asm volatile(
        "mma.sync.aligned.m16n8k8.row.col.f32.tf32.tf32.f32 "
        "{%0,%1,%2,%3}, {%4,%5,%6,%7}, {%8,%9}, {%0,%1,%2,%3};\n"
        : "+f"(c[0]), "+f"(c[1]), "+f"(c[2]), "+f"(c[3])
        : "r"(a0), "r"(a1), "r"(a2), "r"(a3), "r"(b0), "r"(b1));
}

// ---------------------------------------------------------------------------
// TF32 tensor-core GEMM: C[m][n] = sum_k A[m][k]*W[n][k] + bias[n]
// A:[M][K] row-major, W:[N][K] row-major (== B col-major for mma .row.col).
// BM=BN=128, BK=16, 256 threads (8 warps, 2x4), warp tile 64x32.
// smem stride 20 floats -> conflict-free fragment loads (bank=4g+tg).
// ---------------------------------------------------------------------------
#define LDT 20
__global__ __launch_bounds__(256) void sgemm_tf32(
    const float* __restrict__ A, const float* __restrict__ W,
    const float* __restrict__ bias, float* __restrict__ C,
    int M, int N, int K)
{
    __shared__ float As[128 * LDT];
    __shared__ float Ws[128 * LDT];

    const int bm = blockIdx.y * 128, bn = blockIdx.x * 128;
    const int t = threadIdx.x, lane = t & 31, warp = t >> 5;
    const int wm = (warp & 1) * 64, wn = (warp >> 1) * 32;
    const int g = lane >> 2, tg = lane & 3;

    float acc[4][4][4];
#pragma unroll
    for (int i = 0; i < 4; i++)
#pragma unroll
        for (int j = 0; j < 4; j++)
#pragma unroll
            for (int c = 0; c < 4; c++) acc[i][j][c] = 0.f;

    for (int k0 = 0; k0 < K; k0 += 16) {
#pragma unroll
        for (int l = 0; l < 2; l++) {
            int s = t + l * 256;
            int r = s >> 2, c = (s & 3) * 4;
            float4 va = *(const float4*)(A + (size_t)(bm + r) * K + k0 + c);
            va.x = cvt_tf32(va.x); va.y = cvt_tf32(va.y);
            va.z = cvt_tf32(va.z); va.w = cvt_tf32(va.w);
            *(float4*)(As + r * LDT + c) = va;
            float4 vb = *(const float4*)(W + (size_t)(bn + r) * K + k0 + c);
            vb.x = cvt_tf32(vb.x); vb.y = cvt_tf32(vb.y);
            vb.z = cvt_tf32(vb.z); vb.w = cvt_tf32(vb.w);
            *(float4*)(Ws + r * LDT + c) = vb;
        }
        __syncthreads();

#pragma unroll
        for (int ks = 0; ks < 2; ks++) {
            const int kk = ks * 8;
            uint32_t a[4][4], b[4][2];
#pragma unroll
            for (int im = 0; im < 4; im++) {
                const float* p = As + (wm + im * 16 + g) * LDT + kk + tg;
                a[im][0] = __float_as_uint(p[0]);
                a[im][1] = __float_as_uint(p[8 * LDT]);
                a[im][2] = __float_as_uint(p[4]);
                a[im][3] = __float_as_uint(p[8 * LDT + 4]);
            }
#pragma unroll
            for (int jn = 0; jn < 4; jn++) {
                const float* p = Ws + (wn + jn * 8 + g) * LDT + kk + tg;
                b[jn][0] = __float_as_uint(p[0]);
                b[jn][1] = __float_as_uint(p[4]);
            }
#pragma unroll
            for (int im = 0; im < 4; im++)
#pragma unroll
                for (int jn = 0; jn < 4; jn++)
                    mma_tf32(acc[im][jn], a[im][0], a[im][1], a[im][2], a[im][3],
                             b[jn][0], b[jn][1]);
        }
        __syncthreads();
    }

#pragma unroll
    for (int im = 0; im < 4; im++) {
        int r0 = bm + wm + im * 16 + g;
#pragma unroll
        for (int jn = 0; jn < 4; jn++) {
            int c0 = bn + wn + jn * 8 + 2 * tg;
            float bx = bias[c0], by = bias[c0 + 1];
            float2 v0 = make_float2(acc[im][jn][0] + bx, acc[im][jn][1] + by);
            float2 v1 = make_float2(acc[im][jn][2] + bx, acc[im][jn][3] + by);
            *(float2*)(C + (size_t)r0 * N + c0) = v0;
            *(float2*)(C + (size_t)(r0 + 8) * N + c0) = v1;
        }
    }
}

// ---------------------------------------------------------------------------
// LayerNorm over each 64-wide head segment of q and k (in place in g_qkv).
// ---------------------------------------------------------------------------
__global__ __launch_bounds__(256) void qk_layernorm(
    float* __restrict__ qkv, const float* __restrict__ gamma,
    const float* __restrict__ beta)
{
    int gwarp = (blockIdx.x * blockDim.x + threadIdx.x) >> 5;
    int lane  = threadIdx.x & 31;
    int h = gwarp % NHEAD;
    int tmp = gwarp / NHEAD;
    int p = tmp & 1;
    int m = tmp >> 1;
    if (m >= TOKENS) return;

    float* row = qkv + (size_t)m * QKV_N + p * DIM + h * HD;
    float2 v = *(float2*)(row + lane * 2);

    float s = v.x + v.y;
#pragma unroll
    for (int o = 16; o; o >>= 1) s += __shfl_xor_sync(0xffffffffu, s, o);
    float mu = s * (1.f / 64.f);
    float dx = v.x - mu, dy = v.y - mu;
    float vs = dx * dx + dy * dy;
#pragma unroll
    for (int o = 16; o; o >>= 1) vs += __shfl_xor_sync(0xffffffffu, vs, o);
    float rstd = rsqrtf(vs * (1.f / 64.f) + 1e-5f);

    float2 r;
    r.x = dx * rstd * gamma[lane * 2 + 0] + beta[lane * 2 + 0];
    r.y = dy * rstd * gamma[lane * 2 + 1] + beta[lane * 2 + 1];
    *(float2*)(row + lane * 2) = r;
}

// ---------------------------------------------------------------------------
// Flash attention, TF32 mma. Block = (q-tile 64, bh). 128 threads = 4 warps,
// warp w owns rows 16w..16w+15. Q fragments register-resident. Online softmax
// in registers (rows live in one lane-quad). P re-layout via shuffles.
// smem: Ks[64][68], Vs[64][68] (Ks doubles as Q staging at start).
// ---------------------------------------------------------------------------
#define LQ 68
__global__ __launch_bounds__(128) void attn_tf32(
    const float* __restrict__ qkv, float* __restrict__ out)
{
    __shared__ float Ks[64 * LQ];
    __shared__ float Vs[64 * LQ];

    const int q0 = blockIdx.x * 64;
    const int bh = blockIdx.y;
    const int b = bh / NHEAD, h = bh % NHEAD;
    const int t = threadIdx.x, lane = t & 31, warp = t >> 5;
    const int g = lane >> 2, tg = lane & 3;
    const size_t base = (size_t)b * SEQ * QKV_N + (size_t)h * HD;
    const float qscale = 0.125f * 1.4426950408889634f;  // hd^-0.5 * log2(e)

    // Stage Q through Ks, fold scale, convert to tf32
#pragma unroll
    for (int l = 0; l < 8; l++) {
        int s = t + l * 128, r = s >> 4, c = (s & 15) * 4;
        float4 v = *(const float4*)(qkv + base + (size_t)(q0 + r) * QKV_N + c);
        v.x = cvt_tf32(v.x * qscale); v.y = cvt_tf32(v.y * qscale);
        v.z = cvt_tf32(v.z * qscale); v.w = cvt_tf32(v.w * qscale);
        *(float4*)(Ks + r * LQ + c) = v;
    }
    __syncthreads();

    uint32_t Qa[8][4];
#pragma unroll
    for (int kd = 0; kd < 8; kd++) {
        const float* p = Ks + (warp * 16 + g) * LQ + kd * 8 + tg;
        Qa[kd][0] = __float_as_uint(p[0]);
        Qa[kd][1] = __float_as_uint(p[8 * LQ]);
        Qa[kd][2] = __float_as_uint(p[4]);
        Qa[kd][3] = __float_as_uint(p[8 * LQ + 4]);
    }
    __syncthreads();

    float Oacc[8][4];
#pragma unroll
    for (int dn = 0; dn < 8; dn++)
#pragma unroll
        for (int c = 0; c < 4; c++) Oacc[dn][c] = 0.f;
    float m0 = -1e30f, m1 = -1e30f, l0 = 0.f, l1 = 0.f;

    for (int kv = 0; kv < SEQ; kv += 64) {
        // Load K and V tiles (row-major), cvt to tf32
#pragma unroll
        for (int l = 0; l < 8; l++) {
            int s = t + l * 128, r = s >> 4, c = (s & 15) * 4;
            float4 v = *(const float4*)(qkv + base + DIM + (size_t)(kv + r) * QKV_N + c);
            v.x = cvt_tf32(v.x); v.y = cvt_tf32(v.y);
            v.z = cvt_tf32(v.z); v.w = cvt_tf32(v.w);
            *(float4*)(Ks + r * LQ + c) = v;
            float4 w = *(const float4*)(qkv + base + 2 * DIM + (size_t)(kv + r) * QKV_N + c);
            w.x = cvt_tf32(w.x); w.y = cvt_tf32(w.y);
            w.z = cvt_tf32(w.z); w.w = cvt_tf32(w.w);
            *(float4*)(Vs + r * LQ + c) = w;
        }
        __syncthreads();

        // S = Q @ K^T  (in log2 units; scale folded into Q)
        float S[8][4];
#pragma unroll
        for (int jn = 0; jn < 8; jn++)
#pragma unroll
            for (int c = 0; c < 4; c++) S[jn][c] = 0.f;
#pragma unroll
        for (int kd = 0; kd < 8; kd++) {
#pragma unroll
            for (int jn = 0; jn < 8; jn++) {
                const float* p = Ks + (jn * 8 + g) * LQ + kd * 8 + tg;
                uint32_t b0 = __float_as_uint(p[0]);
                uint32_t b1 = __float_as_uint(p[4]);
                mma_tf32(S[jn], Qa[kd][0], Qa[kd][1], Qa[kd][2], Qa[kd][3], b0, b1);
            }
        }

        // Online softmax (row g in regs 0,1; row g+8 in regs 2,3)
        float mx0 = -1e30f, mx1 = -1e30f;
#pragma unroll
        for (int jn = 0; jn < 8; jn++) {
            mx0 = fmaxf(mx0, fmaxf(S[jn][0], S[jn][1]));
            mx1 = fmaxf(mx1, fmaxf(S[jn][2], S[jn][3]));
        }
        mx0 = fmaxf(mx0, __shfl_xor_sync(0xffffffffu, mx0, 1));
        mx0 = fmaxf(mx0, __shfl_xor_sync(0xffffffffu, mx0, 2));
        mx1 = fmaxf(mx1, __shfl_xor_sync(0xffffffffu, mx1, 1));
        mx1 = fmaxf(mx1, __shfl_xor_sync(0xffffffffu, mx1, 2));
        float mn0 = fmaxf(m0, mx0), mn1 = fmaxf(m1, mx1);
        float al0 = ex2f(m0 - mn0), al1 = ex2f(m1 - mn1);
        float s0 = 0.f, s1 = 0.f;
#pragma unroll
        for (int jn = 0; jn < 8; jn++) {
            S[jn][0] = ex2f(S[jn][0] - mn0); s0 += S[jn][0];
            S[jn][1] = ex2f(S[jn][1] - mn0); s0 += S[jn][1];
            S[jn][2] = ex2f(S[jn][2] - mn1); s1 += S[jn][2];
            S[jn][3] = ex2f(S[jn][3] - mn1); s1 += S[jn][3];
        }
        s0 += __shfl_xor_sync(0xffffffffu, s0, 1);
        s0 += __shfl_xor_sync(0xffffffffu, s0, 2);
        s1 += __shfl_xor_sync(0xffffffffu, s1, 1);
        s1 += __shfl_xor_sync(0xffffffffu, s1, 2);
        l0 = l0 * al0 + s0; m0 = mn0;
        l1 = l1 * al1 + s1; m1 = mn1;
#pragma unroll
        for (int dn = 0; dn < 8; dn++) {
            Oacc[dn][0] *= al0; Oacc[dn][1] *= al0;
            Oacc[dn][2] *= al1; Oacc[dn][3] *= al1;
        }

        // O += P @ V  (P a-frags built via shuffles from S c-layout)
        const int srcA = (lane & ~3) | (tg >> 1);
        const int srcB = srcA | 2;
        const bool odd = (tg & 1);
#pragma unroll
        for (int kj = 0; kj < 8; kj++) {
            float x0 = __shfl_sync(0xffffffffu, S[kj][0], srcA);
            float x1 = __shfl_sync(0xffffffffu, S[kj][1], srcA);
            float y0 = __shfl_sync(0xffffffffu, S[kj][0], srcB);
            float y1 = __shfl_sync(0xffffffffu, S[kj][1], srcB);
            float z0 = __shfl_sync(0xffffffffu, S[kj][2], srcA);
            float z1 = __shfl_sync(0xffffffffu, S[kj][3], srcA);
            float w0 = __shfl_sync(0xffffffffu, S[kj][2], srcB);
            float w1 = __shfl_sync(0xffffffffu, S[kj][3], srcB);
            uint32_t a0 = __float_as_uint(cvt_tf32(odd ? x1 : x0));
            uint32_t a2 = __float_as_uint(cvt_tf32(odd ? y1 : y0));
            uint32_t a1 = __float_as_uint(cvt_tf32(odd ? z1 : z0));
            uint32_t a3 = __float_as_uint(cvt_tf32(odd ? w1 : w0));
#pragma unroll
            for (int dn = 0; dn < 8; dn++) {
                const float* p = Vs + (kj * 8 + tg) * LQ + dn * 8 + g;
                uint32_t b0 = __float_as_uint(p[0]);
                uint32_t b1 = __float_as_uint(p[4 * LQ]);
                mma_tf32(Oacc[dn], a0, a1, a2, a3, b0, b1);
            }
        }
        __syncthreads();
    }

    // Epilogue
    float inv0 = 1.f / l0, inv1 = 1.f / l1;
    int r0 = q0 + warp * 16 + g;
#pragma unroll
    for (int dn = 0; dn < 8; dn++) {
        int c0 = h * HD + dn * 8 + 2 * tg;
        float2 v0 = make_float2(Oacc[dn][0] * inv0, Oacc[dn][1] * inv0);
        float2 v1 = make_float2(Oacc[dn][2] * inv1, Oacc[dn][3] * inv1);
        *(float2*)(out + ((size_t)b * SEQ + r0) * DIM + c0) = v0;
        *(float2*)(out + ((size_t)b * SEQ + r0 + 8) * DIM + c0) = v1;
    }
}

// ---------------------------------------------------------------------------
extern "C" void kernel_launch(void* const* d_in, const int* in_sizes, int n_in,
                              void* d_out, int out_size)
{
    const float* x      = (const float*)d_in[0];
    const float* qkv_w  = (const float*)d_in[1];
    const float* qkv_b  = (const float*)d_in[2];
    const float* proj_w = (const float*)d_in[3];
    const float* proj_b = (const float*)d_in[4];
    const float* qn_g   = (const float*)d_in[5];
    const float* qn_b   = (const float*)d_in[6];
    float* out = (float*)d_out;

    float* qkv;  cudaGetSymbolAddress((void**)&qkv, g_qkv);
    float* attn; cudaGetSymbolAddress((void**)&attn, g_attn);

    // 1) QKV projection
    sgemm_tf32<<<dim3(QKV_N / 128, TOKENS / 128), 256>>>(
        x, qkv_w, qkv_b, qkv, TOKENS, QKV_N, DIM);

    // 2) LayerNorm q,k head segments in place
    qk_layernorm<<<TOKENS * 2 * NHEAD * 32 / 256, 256>>>(qkv, qn_g, qn_b);

    // 3) Attention
    attn_tf32<<<dim3(SEQ / 64, BATCH * NHEAD), 128>>>(qkv, attn);

    // 4) Output projection
    sgemm_tf32<<<dim3(DIM / 128, TOKENS / 128), 256>>>(
        attn, proj_w, proj_b, out, TOKENS, DIM, DIM);
}